// round 1
// baseline (speedup 1.0000x reference)
#include <cuda_runtime.h>
#include <cuda_bf16.h>
#include <math.h>

// Problem constants (fixed by dataset)
#define BATCH 512
#define T_IN 64
#define IN_DIM 16
#define HS 32
#define OUT_DIM 32
#define H 960
#define G3 2880
#define T_PRED 48

// Tiling
#define BM 64      // batch tile
#define BJ 32      // hidden-unit tile (x3 gates = 96 output cols)
#define KC 32      // K chunk
#define NTHR 256

// Ping-pong hidden state scratch (device globals: no allocation allowed)
__device__ float g_h0[2][BATCH * H];
__device__ float g_h1[2][BATCH * H];

__device__ __forceinline__ float sigf(float v) {
    return 1.0f / (1.0f + expf(-v));
}

// One fused GRU step for a (BM x BJ) tile:
//   gates = x @ Wih^T (+bih)  and  h @ Whh^T (+bhh), GRU pointwise, h update.
// Writes h_out[b*H + j] and optionally hcat_out[b*hcat_ld + j].
__global__ __launch_bounds__(NTHR, 2)
void gru_step_kernel(const float* __restrict__ x, int ldx, int XK,
                     const float* __restrict__ h_prev,
                     const float* __restrict__ Wih,   // (3H, XK) row-major
                     const float* __restrict__ Whh,   // (3H, H)  row-major
                     const float* __restrict__ bih,
                     const float* __restrict__ bhh,
                     float* __restrict__ h_out,
                     float* __restrict__ hcat_out, int hcat_ld)
{
    __shared__ float As[KC][BM + 1];        // As[k][b], padded
    __shared__ float Bs[3][KC][BJ + 1];     // Bs[g][k][j], padded

    const int tid = threadIdx.x;
    const int j   = tid & 31;    // unit within tile
    const int bg  = tid >> 5;    // warp id -> batch group (8 batches each)
    const int bm0 = blockIdx.x * BM;
    const int j0  = blockIdx.y * BJ;

    float acc_r[8], acc_z[8], acc_in[8], acc_hn[8];
#pragma unroll
    for (int b = 0; b < 8; ++b) { acc_r[b] = 0.f; acc_z[b] = 0.f; acc_in[b] = 0.f; acc_hn[b] = 0.f; }

    // Matmul accumulation helper: acc_r/acc_z shared between phases,
    // gate-2 accumulates into accn (acc_in for x-phase, acc_hn for h-phase).
    auto mm = [&](const float* __restrict__ A, int lda,
                  const float* __restrict__ Wt, int K,
                  float (&accn)[8]) {
        for (int k0 = 0; k0 < K; k0 += KC) {
            // Load A tile: 64 rows x 32 k (zero-pad past K)
#pragma unroll
            for (int i = 0; i < (BM * KC) / NTHR; ++i) {
                int idx = tid + i * NTHR;        // 0..2047
                int r = idx >> 5;                // batch row 0..63
                int c = idx & 31;                // k offset
                float v = (k0 + c < K) ? A[(size_t)(bm0 + r) * lda + k0 + c] : 0.f;
                As[c][r] = v;
            }
            // Load B tile: 96 rows (3 gates x 32 units) x 32 k
#pragma unroll
            for (int i = 0; i < (3 * BJ * KC) / NTHR; ++i) {
                int idx = tid + i * NTHR;        // 0..3071
                int r = idx >> 5;                // 0..95
                int c = idx & 31;
                int g = r >> 5;
                int jj = r & 31;
                float v = (k0 + c < K) ? Wt[(size_t)(g * H + j0 + jj) * K + k0 + c] : 0.f;
                Bs[g][c][jj] = v;
            }
            __syncthreads();
#pragma unroll
            for (int kk = 0; kk < KC; ++kk) {
                float br = Bs[0][kk][j];
                float bz = Bs[1][kk][j];
                float bn = Bs[2][kk][j];
#pragma unroll
                for (int b = 0; b < 8; ++b) {
                    float a = As[kk][bg * 8 + b];   // warp-uniform broadcast
                    acc_r[b] = fmaf(a, br, acc_r[b]);
                    acc_z[b] = fmaf(a, bz, acc_z[b]);
                    accn[b]  = fmaf(a, bn, accn[b]);
                }
            }
            __syncthreads();
        }
    };

    mm(x, ldx, Wih, XK, acc_in);        // gi
    mm(h_prev, H, Whh, H, acc_hn);      // gh

    // Epilogue: GRU gates + state update
    const int jj = j0 + j;
    const float bihr = bih[jj],        bhhr = bhh[jj];
    const float bihz = bih[H + jj],    bhhz = bhh[H + jj];
    const float bihn = bih[2*H + jj],  bhhn = bhh[2*H + jj];

#pragma unroll
    for (int b = 0; b < 8; ++b) {
        int bb = bm0 + bg * 8 + b;
        float hp = h_prev[(size_t)bb * H + jj];
        float r = sigf(acc_r[b] + bihr + bhhr);
        float z = sigf(acc_z[b] + bihz + bhhz);
        float n = tanhf(acc_in[b] + bihn + r * (acc_hn[b] + bhhn));
        float h = (1.0f - z) * n + z * hp;
        h_out[(size_t)bb * H + jj] = h;
        if (hcat_out) hcat_out[(size_t)bb * hcat_ld + jj] = h;
    }
}

// out[b][o] = h[b][:] @ W[o][:] + bias[o] ; out strided by out_ld per batch
__global__ __launch_bounds__(NTHR)
void linear_kernel(const float* __restrict__ h,
                   const float* __restrict__ W,      // (OUT_DIM, H)
                   const float* __restrict__ bias,
                   float* __restrict__ out, int out_ld)
{
    __shared__ float Ws[64][33];   // Ws[k][o], padded
    __shared__ float hs[8][64];
    const int tid = threadIdx.x;
    const int o  = tid & 31;
    const int bl = tid >> 5;       // 0..7
    const int b0 = blockIdx.x * 8;

    float acc = 0.f;
    for (int k0 = 0; k0 < H; k0 += 64) {
#pragma unroll
        for (int i = 0; i < 8; ++i) {
            int idx = tid + i * NTHR;   // 0..2047
            int oo = idx >> 6;          // 0..31
            int kk = idx & 63;
            Ws[kk][oo] = W[(size_t)oo * H + k0 + kk];
        }
#pragma unroll
        for (int i = 0; i < 2; ++i) {
            int idx = tid + i * NTHR;   // 0..511
            int bb = idx >> 6;
            int kk = idx & 63;
            hs[bb][kk] = h[(size_t)(b0 + bb) * H + k0 + kk];
        }
        __syncthreads();
#pragma unroll
        for (int kk = 0; kk < 64; ++kk)
            acc = fmaf(hs[bl][kk], Ws[kk][o], acc);
        __syncthreads();
    }
    out[(size_t)(b0 + bl) * out_ld + o] = acc + bias[o];
}

extern "C" void kernel_launch(void* const* d_in, const int* in_sizes, int n_in,
                              void* d_out, int out_size)
{
    const float* in_data  = (const float*)d_in[0];   // (512, 64, 16)
    const float* last_loc = (const float*)d_in[1];   // (512, 1, 32)
    // d_in[2] = pred_length (fixed 48)
    const float* eWih0 = (const float*)d_in[3];
    const float* eWhh0 = (const float*)d_in[4];
    const float* ebih0 = (const float*)d_in[5];
    const float* ebhh0 = (const float*)d_in[6];
    const float* eWih1 = (const float*)d_in[7];
    const float* eWhh1 = (const float*)d_in[8];
    const float* ebih1 = (const float*)d_in[9];
    const float* ebhh1 = (const float*)d_in[10];
    const float* dWih0 = (const float*)d_in[11];
    const float* dWhh0 = (const float*)d_in[12];
    const float* dbih0 = (const float*)d_in[13];
    const float* dbhh0 = (const float*)d_in[14];
    const float* dWih1 = (const float*)d_in[15];
    const float* dWhh1 = (const float*)d_in[16];
    const float* dbih1 = (const float*)d_in[17];
    const float* dbhh1 = (const float*)d_in[18];
    const float* linW  = (const float*)d_in[19];
    const float* linb  = (const float*)d_in[20];

    float* outputs = (float*)d_out;                            // (512, 48, 32)
    float* hidden  = (float*)d_out + (size_t)BATCH * T_PRED * OUT_DIM;  // (512, 48, 1920)

    float *h0base = nullptr, *h1base = nullptr;
    cudaGetSymbolAddress((void**)&h0base, g_h0);
    cudaGetSymbolAddress((void**)&h1base, g_h1);
    float* h0p[2] = { h0base, h0base + (size_t)BATCH * H };
    float* h1p[2] = { h1base, h1base + (size_t)BATCH * H };

    cudaMemsetAsync(h0p[0], 0, (size_t)BATCH * H * sizeof(float));
    cudaMemsetAsync(h1p[0], 0, (size_t)BATCH * H * sizeof(float));

    dim3 grid(BATCH / BM, H / BJ);   // (8, 30)
    int p0 = 0, p1 = 0;

    // Encoder: 64 steps, 2 layers, interleaved (no ys0 materialization)
    for (int t = 0; t < T_IN; ++t) {
        gru_step_kernel<<<grid, NTHR>>>(in_data + t * IN_DIM, T_IN * IN_DIM, IN_DIM,
                                        h0p[p0], eWih0, eWhh0, ebih0, ebhh0,
                                        h0p[1 - p0], nullptr, 0);
        p0 ^= 1;
        gru_step_kernel<<<grid, NTHR>>>(h0p[p0], H, H,
                                        h1p[p1], eWih1, eWhh1, ebih1, ebhh1,
                                        h1p[1 - p1], nullptr, 0);
        p1 ^= 1;
    }

    // Decoder: 48 steps; hl0/hl1 continue from encoder finals
    const int hid_ld = T_PRED * (2 * H);       // per-batch stride in hidden_outputs
    const int out_ld = T_PRED * OUT_DIM;       // per-batch stride in outputs
    for (int t = 0; t < T_PRED; ++t) {
        const float* x = (t == 0) ? last_loc : (outputs + (size_t)(t - 1) * OUT_DIM);
        int ldx = (t == 0) ? HS : out_ld;
        gru_step_kernel<<<grid, NTHR>>>(x, ldx, HS,
                                        h0p[p0], dWih0, dWhh0, dbih0, dbhh0,
                                        h0p[1 - p0],
                                        hidden + (size_t)t * (2 * H), hid_ld);
        p0 ^= 1;
        gru_step_kernel<<<grid, NTHR>>>(h0p[p0], H, H,
                                        h1p[p1], dWih1, dWhh1, dbih1, dbhh1,
                                        h1p[1 - p1],
                                        hidden + (size_t)t * (2 * H) + H, hid_ld);
        p1 ^= 1;
        linear_kernel<<<BATCH / 8, NTHR>>>(h1p[p1], linW, linb,
                                           outputs + (size_t)t * OUT_DIM, out_ld);
    }
}

// round 3
// speedup vs baseline: 1.7249x; 1.7249x over previous
#include <cuda_runtime.h>
#include <cuda_bf16.h>
#include <math.h>
#include <stdint.h>

// ---------------- problem constants ----------------
#define BATCH 512
#define T_IN 64
#define IN_DIM 16
#define HS 32
#define OUT_DIM 32
#define H 960
#define G3 2880
#define T_PRED 48

#define NC_H 15             // 960/64 K-chunks
#define MTILE 128
#define NTILE 96            // 3 gates x 32 units
#define NTHR 256

// smem: [bias 1024B][stage0][stage1]; rows padded 64->72 elems (144B)
#define ROWB 144
#define ABYTES (MTILE * ROWB)      // 18432
#define BBYTES (NTILE * ROWB)      // 13824
#define STAGE (ABYTES + BBYTES)    // 32256
#define SMEM_BYTES (1024 + 2 * STAGE)   // 65536

// ---------------- device scratch ----------------
#define WBIG (G3 * NC_H * 64)
#define WSM  (G3 * 64)
#define HSN  (NC_H * BATCH * 64)

__device__ __nv_bfloat16 g_Wb[6][2][WBIG];   // [eWhh0,eWih1,eWhh1,dWhh0,dWih1,dWhh1][hi/lo]
__device__ __nv_bfloat16 g_Wsm[2][2][WSM];   // [eWih0,dWih0][hi/lo]
__device__ float g_h0f[2][BATCH * H];
__device__ float g_h1f[2][BATCH * H];
__device__ __nv_bfloat16 g_h0s[2][2][HSN];
__device__ __nv_bfloat16 g_h1s[2][2][HSN];
__device__ __nv_bfloat16 g_xin[2][T_IN * BATCH * 64];
__device__ __nv_bfloat16 g_ll[2][BATCH * 64];
__device__ __nv_bfloat16 g_xd[2][BATCH * 64];

// ---------------- helpers ----------------
__device__ __forceinline__ uint32_t smem_u32(const void* p) {
    uint32_t a;
    asm("{ .reg .u64 t; cvta.to.shared.u64 t, %1; cvt.u32.u64 %0, t; }" : "=r"(a) : "l"(p));
    return a;
}
__device__ __forceinline__ void cp16(uint32_t dst, const void* src) {
    asm volatile("cp.async.cg.shared.global [%0], [%1], 16;" :: "r"(dst), "l"(src) : "memory");
}
#define CP_COMMIT() asm volatile("cp.async.commit_group;" ::: "memory")
#define CP_WAIT1()  asm volatile("cp.async.wait_group 1;" ::: "memory")
#define CP_WAIT0()  asm volatile("cp.async.wait_group 0;" ::: "memory")

__device__ __forceinline__ void mma_bf16(float (&d)[4],
                                         uint32_t a0, uint32_t a1, uint32_t a2, uint32_t a3,
                                         uint32_t b0, uint32_t b1) {
    asm volatile(
        "mma.sync.aligned.m16n8k16.row.col.f32.bf16.bf16.f32 "
        "{%0,%1,%2,%3}, {%4,%5,%6,%7}, {%8,%9}, {%0,%1,%2,%3};"
        : "+f"(d[0]), "+f"(d[1]), "+f"(d[2]), "+f"(d[3])
        : "r"(a0), "r"(a1), "r"(a2), "r"(a3), "r"(b0), "r"(b1));
}
__device__ __forceinline__ uint32_t lds32(uint32_t a) {
    uint32_t v;
    asm volatile("ld.shared.b32 %0, [%1];" : "=r"(v) : "r"(a));
    return v;
}
__device__ __forceinline__ float sigf(float v) { return 1.0f / (1.0f + expf(-v)); }

// ---------------- fused GRU step (mma.sync bf16, split operands) ----------------
__global__ __launch_bounds__(NTHR, 1)
void gru_step_mma(const __nv_bfloat16* __restrict__ xhi, const __nv_bfloat16* __restrict__ xlo, int ncx,
                  const __nv_bfloat16* __restrict__ hhi, const __nv_bfloat16* __restrict__ hlo,
                  const __nv_bfloat16* __restrict__ w1hi, const __nv_bfloat16* __restrict__ w1lo,
                  const __nv_bfloat16* __restrict__ w2hi, const __nv_bfloat16* __restrict__ w2lo,
                  const float* __restrict__ bih, const float* __restrict__ bhh,
                  const float* __restrict__ hprevf, float* __restrict__ houtf,
                  __nv_bfloat16* __restrict__ sohi, __nv_bfloat16* __restrict__ solo,
                  float* __restrict__ hcat, int hcat_ld)
{
    extern __shared__ char smem[];
    float* sbias = (float*)smem;
    const uint32_t sb = smem_u32(smem);

    const int tid  = threadIdx.x;
    const int lane = tid & 31;
    const int w    = tid >> 5;
    const int m0   = blockIdx.x * MTILE;
    const int ub   = blockIdx.y;
    const int s0   = 3 * ncx;
    const int nc   = s0 + 3 * NC_H;

    // biases for this 32-unit block: sbias[0..95]=bih, [96..191]=bhh (gate-major)
    if (tid < 192) {
        int g = (tid < 96) ? (tid >> 5) : ((tid - 96) >> 5);
        int j = tid & 31;
        sbias[tid] = (tid < 96) ? bih[g * H + ub * 32 + j] : bhh[g * H + ub * 32 + j];
    }

    // accumulators
    float accr[4][4], accz[4][4], accnx[4][4], accnh[4][4];
#pragma unroll
    for (int t = 0; t < 4; ++t)
#pragma unroll
        for (int i = 0; i < 4; ++i) { accr[t][i] = 0.f; accz[t][i] = 0.f; accnx[t][i] = 0.f; accnh[t][i] = 0.f; }

    auto issue_load = [&](int c) {
        int seg, ci;
        if (c < s0) { seg = c / ncx; ci = c - seg * ncx; }
        else        { int cc = c - s0; seg = 3 + cc / NC_H; ci = cc - (seg - 3) * NC_H; }
        const __nv_bfloat16* ap = (seg == 2) ? xlo : (seg < 2 ? xhi : (seg == 5 ? hlo : hhi));
        const __nv_bfloat16* bp = (seg == 1) ? w1lo : (seg == 4 ? w2lo : (seg < 3 ? w1hi : w2hi));
        const char* asrc = (const char*)(ap + ((size_t)ci * BATCH + m0) * 64);
        const char* bsrc = (const char*)(bp + ((size_t)ci * G3 + ub * NTILE) * 64);
        uint32_t d = sb + 1024 + (uint32_t)(c & 1) * STAGE;
#pragma unroll
        for (int i = 0; i < 4; ++i) {              // A: 1024 x 16B
            int u = tid + i * NTHR;
            cp16(d + (u >> 3) * ROWB + (u & 7) * 16, asrc + (size_t)u * 16);
        }
#pragma unroll
        for (int i = 0; i < 3; ++i) {              // B: 768 x 16B
            int u = tid + i * NTHR;
            cp16(d + ABYTES + (u >> 3) * ROWB + (u & 7) * 16, bsrc + (size_t)u * 16);
        }
        CP_COMMIT();
    };

    issue_load(0);

#define DO_CHUNK(ACCN)                                                          \
    {                                                                           \
        const uint32_t abase = stage + (w * 16 + (lane >> 2)) * ROWB + (lane & 3) * 4; \
        const uint32_t bbase = stage + ABYTES + (lane >> 2) * ROWB + (lane & 3) * 4;   \
        _Pragma("unroll")                                                       \
        for (int kk = 0; kk < 4; ++kk) {                                        \
            uint32_t a0 = lds32(abase + kk * 32);                               \
            uint32_t a1 = lds32(abase + 8 * ROWB + kk * 32);                    \
            uint32_t a2 = lds32(abase + kk * 32 + 16);                          \
            uint32_t a3 = lds32(abase + 8 * ROWB + kk * 32 + 16);               \
            _Pragma("unroll")                                                   \
            for (int t = 0; t < 4; ++t) {                                       \
                uint32_t bt = bbase + t * 8 * ROWB + kk * 32;                   \
                uint32_t b0 = lds32(bt), b1 = lds32(bt + 16);                   \
                mma_bf16(accr[t], a0, a1, a2, a3, b0, b1);                      \
                b0 = lds32(bt + 32 * ROWB); b1 = lds32(bt + 32 * ROWB + 16);    \
                mma_bf16(accz[t], a0, a1, a2, a3, b0, b1);                      \
                b0 = lds32(bt + 64 * ROWB); b1 = lds32(bt + 64 * ROWB + 16);    \
                mma_bf16(ACCN[t], a0, a1, a2, a3, b0, b1);                      \
            }                                                                   \
        }                                                                       \
    }

    for (int c = 0; c < nc; ++c) {
        if (c + 1 < nc) { issue_load(c + 1); CP_WAIT1(); } else { CP_WAIT0(); }
        __syncthreads();
        const uint32_t stage = sb + 1024 + (uint32_t)(c & 1) * STAGE;
        if (c < s0) DO_CHUNK(accnx) else DO_CHUNK(accnh)
        __syncthreads();
    }
#undef DO_CHUNK

    // ---------------- epilogue ----------------
    const int r0 = m0 + w * 16 + (lane >> 2);
    const int q2 = (lane & 3) * 2;
    const int cj = ub >> 1;            // split-plane chunk
    const int kb = (ub & 1) * 32;

#pragma unroll
    for (int t = 0; t < 4; ++t) {
#pragma unroll
        for (int half = 0; half < 2; ++half) {
            const int row = r0 + half * 8;
            const int jb  = t * 8 + q2;           // unit within block, even
            float hv[2];
#pragma unroll
            for (int e = 0; e < 2; ++e) {
                const int j  = jb + e;
                const int jj = ub * 32 + j;
                const int ai = half * 2 + e;
                float rr = sigf(accr[t][ai] + sbias[j]      + sbias[96 + j]);
                float zz = sigf(accz[t][ai] + sbias[32 + j] + sbias[128 + j]);
                float nn = tanhf(accnx[t][ai] + sbias[64 + j] + rr * (accnh[t][ai] + sbias[160 + j]));
                float hp = __ldg(hprevf + (size_t)row * H + jj);
                hv[e] = (1.0f - zz) * nn + zz * hp;
            }
            const size_t ob = (size_t)row * H + ub * 32 + jb;
            *(float2*)(houtf + ob) = make_float2(hv[0], hv[1]);
            if (hcat)
                *(float2*)(hcat + (size_t)row * hcat_ld + ub * 32 + jb) = make_float2(hv[0], hv[1]);
            __nv_bfloat16 h0 = __float2bfloat16(hv[0]);
            __nv_bfloat16 h1 = __float2bfloat16(hv[1]);
            __nv_bfloat16 l0 = __float2bfloat16(hv[0] - __bfloat162float(h0));
            __nv_bfloat16 l1 = __float2bfloat16(hv[1] - __bfloat162float(h1));
            const size_t so = ((size_t)cj * BATCH + row) * 64 + kb + jb;
            *(__nv_bfloat162*)(sohi + so) = __nv_bfloat162(h0, h1);
            *(__nv_bfloat162*)(solo + so) = __nv_bfloat162(l0, l1);
        }
    }
}

// ---------------- linear head ----------------
__global__ __launch_bounds__(256)
void linear_kernel(const float* __restrict__ h,
                   const float* __restrict__ W, const float* __restrict__ bias,
                   float* __restrict__ out, int out_ld,
                   __nv_bfloat16* __restrict__ xdh, __nv_bfloat16* __restrict__ xdl)
{
    __shared__ float Ws[64][33];
    __shared__ float hs[8][64];
    const int tid = threadIdx.x;
    const int o = tid & 31;
    const int bl = tid >> 5;
    const int b0 = blockIdx.x * 8;

    float acc = 0.f;
    for (int k0 = 0; k0 < H; k0 += 64) {
#pragma unroll
        for (int i = 0; i < 8; ++i) {
            int idx = tid + i * 256;
            Ws[idx & 63][idx >> 6] = W[(size_t)(idx >> 6) * H + k0 + (idx & 63)];
        }
#pragma unroll
        for (int i = 0; i < 2; ++i) {
            int idx = tid + i * 256;
            hs[idx >> 6][idx & 63] = h[(size_t)(b0 + (idx >> 6)) * H + k0 + (idx & 63)];
        }
        __syncthreads();
#pragma unroll
        for (int kk = 0; kk < 64; ++kk)
            acc = fmaf(hs[bl][kk], Ws[kk][o], acc);
        __syncthreads();
    }
    float v = acc + bias[o];
    int b = b0 + bl;
    out[(size_t)b * out_ld + o] = v;
    __nv_bfloat16 hi = __float2bfloat16(v);
    __nv_bfloat16 lo = __float2bfloat16(v - __bfloat162float(hi));
    xdh[(size_t)b * 64 + o] = hi;
    xdl[(size_t)b * 64 + o] = lo;
}

// ---------------- prep kernels ----------------
__global__ void prep_weight(const float* __restrict__ W, int K, int nch,
                            __nv_bfloat16* __restrict__ hi, __nv_bfloat16* __restrict__ lo)
{
    int total = G3 * nch * 64;
    for (int idx = blockIdx.x * blockDim.x + threadIdx.x; idx < total; idx += gridDim.x * blockDim.x) {
        int k = idx & 63;
        int q = idx >> 6;
        int n = q % G3;
        int c = q / G3;
        int ubl = n / 96, rem = n % 96, g = rem >> 5, jj = rem & 31;
        int row = g * H + ubl * 32 + jj;
        int col = c * 64 + k;
        float v = (col < K) ? W[(size_t)row * K + col] : 0.f;
        __nv_bfloat16 h = __float2bfloat16(v);
        hi[idx] = h;
        lo[idx] = __float2bfloat16(v - __bfloat162float(h));
    }
}

__global__ void prep_in(const float* __restrict__ in_data,
                        __nv_bfloat16* __restrict__ hi, __nv_bfloat16* __restrict__ lo)
{
    int total = T_IN * BATCH * 64;
    for (int idx = blockIdx.x * blockDim.x + threadIdx.x; idx < total; idx += gridDim.x * blockDim.x) {
        int k = idx & 63;
        int q = idx >> 6;
        int b = q & (BATCH - 1);
        int t = q >> 9;
        float v = (k < IN_DIM) ? in_data[((size_t)b * T_IN + t) * IN_DIM + k] : 0.f;
        __nv_bfloat16 h = __float2bfloat16(v);
        hi[idx] = h;
        lo[idx] = __float2bfloat16(v - __bfloat162float(h));
    }
}

__global__ void prep_ll(const float* __restrict__ ll_src,
                        __nv_bfloat16* __restrict__ hi, __nv_bfloat16* __restrict__ lo)
{
    int total = BATCH * 64;
    for (int idx = blockIdx.x * blockDim.x + threadIdx.x; idx < total; idx += gridDim.x * blockDim.x) {
        int k = idx & 63;
        int b = idx >> 6;
        float v = (k < HS) ? ll_src[(size_t)b * HS + k] : 0.f;
        __nv_bfloat16 h = __float2bfloat16(v);
        hi[idx] = h;
        lo[idx] = __float2bfloat16(v - __bfloat162float(h));
    }
}

// ---------------- host ----------------
extern "C" void kernel_launch(void* const* d_in, const int* in_sizes, int n_in,
                              void* d_out, int out_size)
{
    const float* in_data  = (const float*)d_in[0];
    const float* last_loc = (const float*)d_in[1];
    const float* eWih0 = (const float*)d_in[3];
    const float* eWhh0 = (const float*)d_in[4];
    const float* ebih0 = (const float*)d_in[5];
    const float* ebhh0 = (const float*)d_in[6];
    const float* eWih1 = (const float*)d_in[7];
    const float* eWhh1 = (const float*)d_in[8];
    const float* ebih1 = (const float*)d_in[9];
    const float* ebhh1 = (const float*)d_in[10];
    const float* dWih0 = (const float*)d_in[11];
    const float* dWhh0 = (const float*)d_in[12];
    const float* dbih0 = (const float*)d_in[13];
    const float* dbhh0 = (const float*)d_in[14];
    const float* dWih1 = (const float*)d_in[15];
    const float* dWhh1 = (const float*)d_in[16];
    const float* dbih1 = (const float*)d_in[17];
    const float* dbhh1 = (const float*)d_in[18];
    const float* linW  = (const float*)d_in[19];
    const float* linb  = (const float*)d_in[20];

    float* outputs = (float*)d_out;
    float* hidden  = (float*)d_out + (size_t)BATCH * T_PRED * OUT_DIM;

    __nv_bfloat16 (*Wb)[2][WBIG];   cudaGetSymbolAddress((void**)&Wb, g_Wb);
    __nv_bfloat16 (*Wsm)[2][WSM];   cudaGetSymbolAddress((void**)&Wsm, g_Wsm);
    float (*h0f)[BATCH * H];        cudaGetSymbolAddress((void**)&h0f, g_h0f);
    float (*h1f)[BATCH * H];        cudaGetSymbolAddress((void**)&h1f, g_h1f);
    __nv_bfloat16 (*h0s)[2][HSN];   cudaGetSymbolAddress((void**)&h0s, g_h0s);
    __nv_bfloat16 (*h1s)[2][HSN];   cudaGetSymbolAddress((void**)&h1s, g_h1s);
    __nv_bfloat16 (*xin)[T_IN * BATCH * 64]; cudaGetSymbolAddress((void**)&xin, g_xin);
    __nv_bfloat16 (*xll)[BATCH * 64];        cudaGetSymbolAddress((void**)&xll, g_ll);
    __nv_bfloat16 (*xd)[BATCH * 64];         cudaGetSymbolAddress((void**)&xd, g_xd);

    cudaFuncSetAttribute(gru_step_mma, cudaFuncAttributeMaxDynamicSharedMemorySize, SMEM_BYTES);

    prep_weight<<<1024, 256>>>(eWhh0, H,  NC_H, Wb[0][0], Wb[0][1]);
    prep_weight<<<1024, 256>>>(eWih1, H,  NC_H, Wb[1][0], Wb[1][1]);
    prep_weight<<<1024, 256>>>(eWhh1, H,  NC_H, Wb[2][0], Wb[2][1]);
    prep_weight<<<1024, 256>>>(dWhh0, H,  NC_H, Wb[3][0], Wb[3][1]);
    prep_weight<<<1024, 256>>>(dWih1, H,  NC_H, Wb[4][0], Wb[4][1]);
    prep_weight<<<1024, 256>>>(dWhh1, H,  NC_H, Wb[5][0], Wb[5][1]);
    prep_weight<<<256, 256>>>(eWih0, IN_DIM, 1, Wsm[0][0], Wsm[0][1]);
    prep_weight<<<256, 256>>>(dWih0, HS,     1, Wsm[1][0], Wsm[1][1]);
    prep_in<<<512, 256>>>(in_data, xin[0], xin[1]);
    prep_ll<<<64, 256>>>(last_loc, xll[0], xll[1]);

    cudaMemsetAsync(h0f[0], 0, (size_t)BATCH * H * sizeof(float));
    cudaMemsetAsync(h1f[0], 0, (size_t)BATCH * H * sizeof(float));
    cudaMemsetAsync(h0s[0], 0, (size_t)2 * HSN * sizeof(__nv_bfloat16));
    cudaMemsetAsync(h1s[0], 0, (size_t)2 * HSN * sizeof(__nv_bfloat16));

    dim3 grid(BATCH / MTILE, H / 32);   // (4, 30)
    int p0 = 0, p1 = 0;
    const int out_ld = T_PRED * OUT_DIM;
    const int hid_ld = T_PRED * 2 * H;

    // ---- encoder ----
    for (int t = 0; t < T_IN; ++t) {
        gru_step_mma<<<grid, NTHR, SMEM_BYTES>>>(
            xin[0] + (size_t)t * BATCH * 64, xin[1] + (size_t)t * BATCH * 64, 1,
            h0s[p0][0], h0s[p0][1],
            Wsm[0][0], Wsm[0][1], Wb[0][0], Wb[0][1],
            ebih0, ebhh0, h0f[p0], h0f[1 - p0],
            h0s[1 - p0][0], h0s[1 - p0][1], nullptr, 0);
        p0 ^= 1;
        gru_step_mma<<<grid, NTHR, SMEM_BYTES>>>(
            h0s[p0][0], h0s[p0][1], NC_H,
            h1s[p1][0], h1s[p1][1],
            Wb[1][0], Wb[1][1], Wb[2][0], Wb[2][1],
            ebih1, ebhh1, h1f[p1], h1f[1 - p1],
            h1s[1 - p1][0], h1s[1 - p1][1], nullptr, 0);
        p1 ^= 1;
    }

    // ---- decoder ----
    for (int t = 0; t < T_PRED; ++t) {
        const __nv_bfloat16* xh = (t == 0) ? xll[0] : xd[0];
        const __nv_bfloat16* xl = (t == 0) ? xll[1] : xd[1];
        gru_step_mma<<<grid, NTHR, SMEM_BYTES>>>(
            xh, xl, 1,
            h0s[p0][0], h0s[p0][1],
            Wsm[1][0], Wsm[1][1], Wb[3][0], Wb[3][1],
            dbih0, dbhh0, h0f[p0], h0f[1 - p0],
            h0s[1 - p0][0], h0s[1 - p0][1],
            hidden + (size_t)t * 2 * H, hid_ld);
        p0 ^= 1;
        gru_step_mma<<<grid, NTHR, SMEM_BYTES>>>(
            h0s[p0][0], h0s[p0][1], NC_H,
            h1s[p1][0], h1s[p1][1],
            Wb[4][0], Wb[4][1], Wb[5][0], Wb[5][1],
            dbih1, dbhh1, h1f[p1], h1f[1 - p1],
            h1s[1 - p1][0], h1s[1 - p1][1],
            hidden + (size_t)t * 2 * H + H, hid_ld);
        p1 ^= 1;
        linear_kernel<<<BATCH / 8, 256>>>(h1f[p1], linW, linb,
                                          outputs + (size_t)t * OUT_DIM, out_ld,
                                          xd[0], xd[1]);
    }
}

// round 4
// speedup vs baseline: 1.8030x; 1.0452x over previous
#include <cuda_runtime.h>
#include <cuda_bf16.h>
#include <math.h>
#include <stdint.h>

// ---------------- problem constants ----------------
#define BATCH 512
#define T_IN 64
#define IN_DIM 16
#define HS 32
#define OUT_DIM 32
#define H 960
#define G3 2880
#define T_PRED 48

#define NC_H 15             // 960/64 K-chunks
#define MTILE 128
#define NTILE 96            // 3 gates x 32 units
#define NTHR 256

// smem: [bias 1024B][3 stages]; rows padded 64 elems -> 144B
#define ROWB 144
#define ABYTES (MTILE * ROWB)      // 18432
#define BBYTES (NTILE * ROWB)      // 13824
#define STAGE (ABYTES + BBYTES)    // 32256
#define SMEM_BYTES (1024 + 3 * STAGE)   // 97792
// epilogue planes (reuse stage area): M 128x100 fp32, N2 128x36 fp32
#define MSTRIDE 100
#define N2STRIDE 36
#define N2OFF 51200

// ---------------- device scratch ----------------
#define WBIG (G3 * NC_H * 64)
#define WSM  (G3 * 64)
#define HSN  (NC_H * BATCH * 64)

__device__ __nv_bfloat16 g_Wb[6][2][WBIG];   // [eWhh0,eWih1,eWhh1,dWhh0,dWih1,dWhh1][hi/lo]
__device__ __nv_bfloat16 g_Wsm[2][2][WSM];   // [eWih0,dWih0][hi/lo]
__device__ float g_h0f[2][BATCH * H];
__device__ float g_h1f[2][BATCH * H];
__device__ __nv_bfloat16 g_h0s[2][2][HSN];
__device__ __nv_bfloat16 g_h1s[2][2][HSN];
__device__ __nv_bfloat16 g_xin[2][T_IN * BATCH * 64];
__device__ __nv_bfloat16 g_ll[2][BATCH * 64];
__device__ __nv_bfloat16 g_xd[2][BATCH * 64];

// ---------------- helpers ----------------
__device__ __forceinline__ uint32_t smem_u32(const void* p) {
    uint32_t a;
    asm("{ .reg .u64 t; cvta.to.shared.u64 t, %1; cvt.u32.u64 %0, t; }" : "=r"(a) : "l"(p));
    return a;
}
__device__ __forceinline__ void cp16(uint32_t dst, const void* src) {
    asm volatile("cp.async.cg.shared.global [%0], [%1], 16;" :: "r"(dst), "l"(src) : "memory");
}
#define CP_COMMIT() asm volatile("cp.async.commit_group;" ::: "memory")
#define CP_WAIT(n)  asm volatile("cp.async.wait_group %0;" :: "n"(n) : "memory")

__device__ __forceinline__ void ldm4(uint32_t (&r)[4], uint32_t a) {
    asm volatile("ldmatrix.sync.aligned.m8n8.x4.shared.b16 {%0,%1,%2,%3}, [%4];"
        : "=r"(r[0]), "=r"(r[1]), "=r"(r[2]), "=r"(r[3]) : "r"(a));
}
__device__ __forceinline__ void mma_bf16(float (&d)[4], const uint32_t (&a)[4],
                                         uint32_t b0, uint32_t b1) {
    asm volatile(
        "mma.sync.aligned.m16n8k16.row.col.f32.bf16.bf16.f32 "
        "{%0,%1,%2,%3}, {%4,%5,%6,%7}, {%8,%9}, {%0,%1,%2,%3};"
        : "+f"(d[0]), "+f"(d[1]), "+f"(d[2]), "+f"(d[3])
        : "r"(a[0]), "r"(a[1]), "r"(a[2]), "r"(a[3]), "r"(b0), "r"(b1));
}
__device__ __forceinline__ float sigf(float v) { return 1.0f / (1.0f + expf(-v)); }

// ---------------- fused GRU step (mma.sync bf16, ldmatrix, 3-stage) ----------------
__global__ __launch_bounds__(NTHR, 1)
void gru_step_mma(const __nv_bfloat16* __restrict__ xhi, const __nv_bfloat16* __restrict__ xlo, int ncx,
                  const __nv_bfloat16* __restrict__ hhi, const __nv_bfloat16* __restrict__ hlo,
                  const __nv_bfloat16* __restrict__ w1hi, const __nv_bfloat16* __restrict__ w1lo,
                  const __nv_bfloat16* __restrict__ w2hi, const __nv_bfloat16* __restrict__ w2lo,
                  const float* __restrict__ bih, const float* __restrict__ bhh,
                  const float* __restrict__ hprevf, float* __restrict__ houtf,
                  __nv_bfloat16* __restrict__ sohi, __nv_bfloat16* __restrict__ solo,
                  float* __restrict__ hcat, int hcat_ld)
{
    extern __shared__ char smem[];
    float* sbias = (float*)smem;
    const uint32_t sb = smem_u32(smem);

    const int tid  = threadIdx.x;
    const int lane = tid & 31;
    const int w    = tid >> 5;
    const int wm   = w & 3;      // m-block (32 rows)
    const int wn   = w >> 2;     // n-half (48 cols)
    const int m0   = blockIdx.x * MTILE;
    const int ub   = blockIdx.y;
    const int s0   = 3 * ncx;
    const int nc   = s0 + 3 * NC_H;

    if (tid < 192) {
        int g = (tid < 96) ? (tid >> 5) : ((tid - 96) >> 5);
        int j = tid & 31;
        sbias[tid] = (tid < 96) ? bih[g * H + ub * 32 + j] : bhh[g * H + ub * 32 + j];
    }

    // accumulators: acc = r/z (both passes) + n-gate x-pass; accn = n-gate h-pass (wn==1)
    float acc[2][6][4];
    float accn[2][4][4];
#pragma unroll
    for (int m2 = 0; m2 < 2; ++m2) {
#pragma unroll
        for (int f = 0; f < 6; ++f)
#pragma unroll
            for (int i = 0; i < 4; ++i) acc[m2][f][i] = 0.f;
#pragma unroll
        for (int f = 0; f < 4; ++f)
#pragma unroll
            for (int i = 0; i < 4; ++i) accn[m2][f][i] = 0.f;
    }

    // ldmatrix lane address offsets (within stage)
    const int lrow = (lane & 7) + ((lane >> 3) & 1) * 8;
    const int lcol = (lane >> 4) * 16;                       // bytes
    const uint32_t aoff = (uint32_t)(wm * 32 + lrow) * ROWB + lcol;
    const uint32_t boff = ABYTES + (uint32_t)(wn * 48 + lrow) * ROWB + lcol;

    auto issue_load = [&](int c) {
        int seg, ci;
        if (c < s0) { seg = c / ncx; ci = c - seg * ncx; }
        else        { int cc = c - s0; seg = 3 + cc / NC_H; ci = cc - (seg - 3) * NC_H; }
        const __nv_bfloat16* ap = (seg == 2) ? xlo : (seg < 2 ? xhi : (seg == 5 ? hlo : hhi));
        const __nv_bfloat16* bp = (seg == 1) ? w1lo : (seg == 4 ? w2lo : (seg < 3 ? w1hi : w2hi));
        const char* asrc = (const char*)(ap + ((size_t)ci * BATCH + m0) * 64);
        const char* bsrc = (const char*)(bp + ((size_t)ci * G3 + ub * NTILE) * 64);
        uint32_t d = sb + 1024 + (uint32_t)(c % 3) * STAGE;
#pragma unroll
        for (int i = 0; i < 4; ++i) {              // A: 1024 x 16B
            int u = tid + i * NTHR;
            cp16(d + (u >> 3) * ROWB + (u & 7) * 16, asrc + (size_t)u * 16);
        }
#pragma unroll
        for (int i = 0; i < 3; ++i) {              // B: 768 x 16B
            int u = tid + i * NTHR;
            cp16(d + ABYTES + (u >> 3) * ROWB + (u & 7) * 16, bsrc + (size_t)u * 16);
        }
        CP_COMMIT();
    };

    issue_load(0); issue_load(1); issue_load(2);

#define CHUNK_BODY(SPLIT)                                                       \
    {                                                                           \
        _Pragma("unroll")                                                       \
        for (int kk = 0; kk < 4; ++kk) {                                        \
            uint32_t a0[4], a1[4], b0[4], b1[4], b2[4];                         \
            ldm4(a0, stage + aoff + kk * 32);                                   \
            ldm4(a1, stage + aoff + 16 * ROWB + kk * 32);                       \
            ldm4(b0, stage + boff + kk * 32);                                   \
            ldm4(b1, stage + boff + 16 * ROWB + kk * 32);                       \
            ldm4(b2, stage + boff + 32 * ROWB + kk * 32);                       \
            mma_bf16(acc[0][0], a0, b0[0], b0[2]);                              \
            mma_bf16(acc[1][0], a1, b0[0], b0[2]);                              \
            mma_bf16(acc[0][1], a0, b0[1], b0[3]);                              \
            mma_bf16(acc[1][1], a1, b0[1], b0[3]);                              \
            if (SPLIT) {                                                        \
                mma_bf16(accn[0][0], a0, b1[0], b1[2]);                         \
                mma_bf16(accn[1][0], a1, b1[0], b1[2]);                         \
                mma_bf16(accn[0][1], a0, b1[1], b1[3]);                         \
                mma_bf16(accn[1][1], a1, b1[1], b1[3]);                         \
                mma_bf16(accn[0][2], a0, b2[0], b2[2]);                         \
                mma_bf16(accn[1][2], a1, b2[0], b2[2]);                         \
                mma_bf16(accn[0][3], a0, b2[1], b2[3]);                         \
                mma_bf16(accn[1][3], a1, b2[1], b2[3]);                         \
            } else {                                                            \
                mma_bf16(acc[0][2], a0, b1[0], b1[2]);                          \
                mma_bf16(acc[1][2], a1, b1[0], b1[2]);                          \
                mma_bf16(acc[0][3], a0, b1[1], b1[3]);                          \
                mma_bf16(acc[1][3], a1, b1[1], b1[3]);                          \
                mma_bf16(acc[0][4], a0, b2[0], b2[2]);                          \
                mma_bf16(acc[1][4], a1, b2[0], b2[2]);                          \
                mma_bf16(acc[0][5], a0, b2[1], b2[3]);                          \
                mma_bf16(acc[1][5], a1, b2[1], b2[3]);                          \
            }                                                                   \
        }                                                                       \
    }

    for (int c = 0; c < nc; ++c) {
        if (c + 2 < nc)      { CP_WAIT(2); }
        else if (c + 1 < nc) { CP_WAIT(1); }
        else                 { CP_WAIT(0); }
        __syncthreads();
        const uint32_t stage = sb + 1024 + (uint32_t)(c % 3) * STAGE;
        // h-pass n-gate goes to accn in wn==1 warps; everything else to acc
        if (c >= s0 && wn == 1) CHUNK_BODY(1) else CHUNK_BODY(0)
        __syncthreads();
        if (c + 3 < nc) issue_load(c + 3);
    }
#undef CHUNK_BODY

    // ---------------- epilogue: accums -> smem planes -> gate math ----------------
    float* Mp = (float*)(smem + 1024);
    float* Np = (float*)(smem + 1024 + N2OFF);
    {
        const int rb = wm * 32 + (lane >> 2);
        const int cb = wn * 48 + (lane & 3) * 2;
#pragma unroll
        for (int m2 = 0; m2 < 2; ++m2) {
#pragma unroll
            for (int f = 0; f < 6; ++f) {
                int r = rb + m2 * 16;
                int cc = cb + f * 8;
                *(float2*)&Mp[r * MSTRIDE + cc]       = make_float2(acc[m2][f][0], acc[m2][f][1]);
                *(float2*)&Mp[(r + 8) * MSTRIDE + cc] = make_float2(acc[m2][f][2], acc[m2][f][3]);
            }
        }
        if (wn == 1) {
            const int cb2 = (lane & 3) * 2;
#pragma unroll
            for (int m2 = 0; m2 < 2; ++m2) {
#pragma unroll
                for (int f = 0; f < 4; ++f) {
                    int r = rb + m2 * 16;
                    int cc = cb2 + f * 8;
                    *(float2*)&Np[r * N2STRIDE + cc]       = make_float2(accn[m2][f][0], accn[m2][f][1]);
                    *(float2*)&Np[(r + 8) * N2STRIDE + cc] = make_float2(accn[m2][f][2], accn[m2][f][3]);
                }
            }
        }
    }
    __syncthreads();

    {
        const int row = tid >> 1;            // CTA-local batch row
        const int j0  = (tid & 1) * 16;      // unit group start
        const int brow = m0 + row;
        const int cj = ub >> 1;
        const int kb = (ub & 1) * 32;

        float hv[16];
#pragma unroll
        for (int v = 0; v < 8; ++v) {
            int j = j0 + v * 2;
            float2 R  = *(float2*)&Mp[row * MSTRIDE + j];
            float2 Z  = *(float2*)&Mp[row * MSTRIDE + 32 + j];
            float2 NX = *(float2*)&Mp[row * MSTRIDE + 64 + j];
            float2 NH = *(float2*)&Np[row * N2STRIDE + j];
            float2 HP = *(const float2*)(hprevf + (size_t)brow * H + ub * 32 + j);
#pragma unroll
            for (int e = 0; e < 2; ++e) {
                int jj = j + e;
                float rr = sigf(((e ? R.y : R.x))  + sbias[jj]      + sbias[96 + jj]);
                float zz = sigf(((e ? Z.y : Z.x))  + sbias[32 + jj] + sbias[128 + jj]);
                float nn = tanhf(((e ? NX.y : NX.x)) + sbias[64 + jj]
                                 + rr * (((e ? NH.y : NH.x)) + sbias[160 + jj]));
                hv[j - j0 + e] = (1.0f - zz) * nn + zz * (e ? HP.y : HP.x);
            }
        }
        // fp32 state + hcat
        const size_t ob = (size_t)brow * H + ub * 32 + j0;
#pragma unroll
        for (int q = 0; q < 4; ++q)
            *(float4*)(houtf + ob + q * 4) = make_float4(hv[q*4], hv[q*4+1], hv[q*4+2], hv[q*4+3]);
        if (hcat) {
            const size_t cbo = (size_t)brow * hcat_ld + ub * 32 + j0;
#pragma unroll
            for (int q = 0; q < 4; ++q)
                *(float4*)(hcat + cbo + q * 4) = make_float4(hv[q*4], hv[q*4+1], hv[q*4+2], hv[q*4+3]);
        }
        // split-bf16 planes for next step
        __nv_bfloat162 hh[8], ll[8];
#pragma unroll
        for (int i = 0; i < 8; ++i) {
            __nv_bfloat16 a = __float2bfloat16(hv[2*i]);
            __nv_bfloat16 b = __float2bfloat16(hv[2*i+1]);
            __nv_bfloat16 al = __float2bfloat16(hv[2*i]   - __bfloat162float(a));
            __nv_bfloat16 bl = __float2bfloat16(hv[2*i+1] - __bfloat162float(b));
            hh[i] = __nv_bfloat162(a, b);
            ll[i] = __nv_bfloat162(al, bl);
        }
        const size_t so = ((size_t)cj * BATCH + brow) * 64 + kb + j0;
        *(uint4*)(sohi + so)     = ((uint4*)hh)[0];
        *(uint4*)(sohi + so + 8) = ((uint4*)hh)[1];
        *(uint4*)(solo + so)     = ((uint4*)ll)[0];
        *(uint4*)(solo + so + 8) = ((uint4*)ll)[1];
    }
}

// ---------------- linear head ----------------
__global__ __launch_bounds__(256)
void linear_kernel(const float* __restrict__ h,
                   const float* __restrict__ W, const float* __restrict__ bias,
                   float* __restrict__ out, int out_ld,
                   __nv_bfloat16* __restrict__ xdh, __nv_bfloat16* __restrict__ xdl)
{
    __shared__ float Ws[64][33];
    __shared__ float hs[8][64];
    const int tid = threadIdx.x;
    const int o = tid & 31;
    const int bl = tid >> 5;
    const int b0 = blockIdx.x * 8;

    float acc = 0.f;
    for (int k0 = 0; k0 < H; k0 += 64) {
#pragma unroll
        for (int i = 0; i < 8; ++i) {
            int idx = tid + i * 256;
            Ws[idx & 63][idx >> 6] = W[(size_t)(idx >> 6) * H + k0 + (idx & 63)];
        }
#pragma unroll
        for (int i = 0; i < 2; ++i) {
            int idx = tid + i * 256;
            hs[idx >> 6][idx & 63] = h[(size_t)(b0 + (idx >> 6)) * H + k0 + (idx & 63)];
        }
        __syncthreads();
#pragma unroll
        for (int kk = 0; kk < 64; ++kk)
            acc = fmaf(hs[bl][kk], Ws[kk][o], acc);
        __syncthreads();
    }
    float v = acc + bias[o];
    int b = b0 + bl;
    out[(size_t)b * out_ld + o] = v;
    __nv_bfloat16 hi = __float2bfloat16(v);
    __nv_bfloat16 lo = __float2bfloat16(v - __bfloat162float(hi));
    xdh[(size_t)b * 64 + o] = hi;
    xdl[(size_t)b * 64 + o] = lo;
}

// ---------------- prep kernels ----------------
__global__ void prep_weight(const float* __restrict__ W, int K, int nch,
                            __nv_bfloat16* __restrict__ hi, __nv_bfloat16* __restrict__ lo)
{
    int total = G3 * nch * 64;
    for (int idx = blockIdx.x * blockDim.x + threadIdx.x; idx < total; idx += gridDim.x * blockDim.x) {
        int k = idx & 63;
        int q = idx >> 6;
        int n = q % G3;
        int c = q / G3;
        int ubl = n / 96, rem = n % 96, g = rem >> 5, jj = rem & 31;
        int row = g * H + ubl * 32 + jj;
        int col = c * 64 + k;
        float v = (col < K) ? W[(size_t)row * K + col] : 0.f;
        __nv_bfloat16 h = __float2bfloat16(v);
        hi[idx] = h;
        lo[idx] = __float2bfloat16(v - __bfloat162float(h));
    }
}

__global__ void prep_in(const float* __restrict__ in_data,
                        __nv_bfloat16* __restrict__ hi, __nv_bfloat16* __restrict__ lo)
{
    int total = T_IN * BATCH * 64;
    for (int idx = blockIdx.x * blockDim.x + threadIdx.x; idx < total; idx += gridDim.x * blockDim.x) {
        int k = idx & 63;
        int q = idx >> 6;
        int b = q & (BATCH - 1);
        int t = q >> 9;
        float v = (k < IN_DIM) ? in_data[((size_t)b * T_IN + t) * IN_DIM + k] : 0.f;
        __nv_bfloat16 h = __float2bfloat16(v);
        hi[idx] = h;
        lo[idx] = __float2bfloat16(v - __bfloat162float(h));
    }
}

__global__ void prep_ll(const float* __restrict__ ll_src,
                        __nv_bfloat16* __restrict__ hi, __nv_bfloat16* __restrict__ lo)
{
    int total = BATCH * 64;
    for (int idx = blockIdx.x * blockDim.x + threadIdx.x; idx < total; idx += gridDim.x * blockDim.x) {
        int k = idx & 63;
        int b = idx >> 6;
        float v = (k < HS) ? ll_src[(size_t)b * HS + k] : 0.f;
        __nv_bfloat16 h = __float2bfloat16(v);
        hi[idx] = h;
        lo[idx] = __float2bfloat16(v - __bfloat162float(h));
    }
}

// ---------------- host ----------------
extern "C" void kernel_launch(void* const* d_in, const int* in_sizes, int n_in,
                              void* d_out, int out_size)
{
    const float* in_data  = (const float*)d_in[0];
    const float* last_loc = (const float*)d_in[1];
    const float* eWih0 = (const float*)d_in[3];
    const float* eWhh0 = (const float*)d_in[4];
    const float* ebih0 = (const float*)d_in[5];
    const float* ebhh0 = (const float*)d_in[6];
    const float* eWih1 = (const float*)d_in[7];
    const float* eWhh1 = (const float*)d_in[8];
    const float* ebih1 = (const float*)d_in[9];
    const float* ebhh1 = (const float*)d_in[10];
    const float* dWih0 = (const float*)d_in[11];
    const float* dWhh0 = (const float*)d_in[12];
    const float* dbih0 = (const float*)d_in[13];
    const float* dbhh0 = (const float*)d_in[14];
    const float* dWih1 = (const float*)d_in[15];
    const float* dWhh1 = (const float*)d_in[16];
    const float* dbih1 = (const float*)d_in[17];
    const float* dbhh1 = (const float*)d_in[18];
    const float* linW  = (const float*)d_in[19];
    const float* linb  = (const float*)d_in[20];

    float* outputs = (float*)d_out;
    float* hidden  = (float*)d_out + (size_t)BATCH * T_PRED * OUT_DIM;

    __nv_bfloat16 (*Wb)[2][WBIG];   cudaGetSymbolAddress((void**)&Wb, g_Wb);
    __nv_bfloat16 (*Wsm)[2][WSM];   cudaGetSymbolAddress((void**)&Wsm, g_Wsm);
    float (*h0f)[BATCH * H];        cudaGetSymbolAddress((void**)&h0f, g_h0f);
    float (*h1f)[BATCH * H];        cudaGetSymbolAddress((void**)&h1f, g_h1f);
    __nv_bfloat16 (*h0s)[2][HSN];   cudaGetSymbolAddress((void**)&h0s, g_h0s);
    __nv_bfloat16 (*h1s)[2][HSN];   cudaGetSymbolAddress((void**)&h1s, g_h1s);
    __nv_bfloat16 (*xin)[T_IN * BATCH * 64]; cudaGetSymbolAddress((void**)&xin, g_xin);
    __nv_bfloat16 (*xll)[BATCH * 64];        cudaGetSymbolAddress((void**)&xll, g_ll);
    __nv_bfloat16 (*xd)[BATCH * 64];         cudaGetSymbolAddress((void**)&xd, g_xd);

    cudaFuncSetAttribute(gru_step_mma, cudaFuncAttributeMaxDynamicSharedMemorySize, SMEM_BYTES);

    prep_weight<<<1024, 256>>>(eWhh0, H,  NC_H, Wb[0][0], Wb[0][1]);
    prep_weight<<<1024, 256>>>(eWih1, H,  NC_H, Wb[1][0], Wb[1][1]);
    prep_weight<<<1024, 256>>>(eWhh1, H,  NC_H, Wb[2][0], Wb[2][1]);
    prep_weight<<<1024, 256>>>(dWhh0, H,  NC_H, Wb[3][0], Wb[3][1]);
    prep_weight<<<1024, 256>>>(dWih1, H,  NC_H, Wb[4][0], Wb[4][1]);
    prep_weight<<<1024, 256>>>(dWhh1, H,  NC_H, Wb[5][0], Wb[5][1]);
    prep_weight<<<256, 256>>>(eWih0, IN_DIM, 1, Wsm[0][0], Wsm[0][1]);
    prep_weight<<<256, 256>>>(dWih0, HS,     1, Wsm[1][0], Wsm[1][1]);
    prep_in<<<512, 256>>>(in_data, xin[0], xin[1]);
    prep_ll<<<64, 256>>>(last_loc, xll[0], xll[1]);

    cudaMemsetAsync(h0f[0], 0, (size_t)BATCH * H * sizeof(float));
    cudaMemsetAsync(h1f[0], 0, (size_t)BATCH * H * sizeof(float));
    cudaMemsetAsync(h0s[0], 0, (size_t)2 * HSN * sizeof(__nv_bfloat16));
    cudaMemsetAsync(h1s[0], 0, (size_t)2 * HSN * sizeof(__nv_bfloat16));

    dim3 grid(BATCH / MTILE, H / 32);   // (4, 30)
    int p0 = 0, p1 = 0;
    const int out_ld = T_PRED * OUT_DIM;
    const int hid_ld = T_PRED * 2 * H;

    // ---- encoder ----
    for (int t = 0; t < T_IN; ++t) {
        gru_step_mma<<<grid, NTHR, SMEM_BYTES>>>(
            xin[0] + (size_t)t * BATCH * 64, xin[1] + (size_t)t * BATCH * 64, 1,
            h0s[p0][0], h0s[p0][1],
            Wsm[0][0], Wsm[0][1], Wb[0][0], Wb[0][1],
            ebih0, ebhh0, h0f[p0], h0f[1 - p0],
            h0s[1 - p0][0], h0s[1 - p0][1], nullptr, 0);
        p0 ^= 1;
        gru_step_mma<<<grid, NTHR, SMEM_BYTES>>>(
            h0s[p0][0], h0s[p0][1], NC_H,
            h1s[p1][0], h1s[p1][1],
            Wb[1][0], Wb[1][1], Wb[2][0], Wb[2][1],
            ebih1, ebhh1, h1f[p1], h1f[1 - p1],
            h1s[1 - p1][0], h1s[1 - p1][1], nullptr, 0);
        p1 ^= 1;
    }

    // ---- decoder ----
    for (int t = 0; t < T_PRED; ++t) {
        const __nv_bfloat16* xh = (t == 0) ? xll[0] : xd[0];
        const __nv_bfloat16* xl = (t == 0) ? xll[1] : xd[1];
        gru_step_mma<<<grid, NTHR, SMEM_BYTES>>>(
            xh, xl, 1,
            h0s[p0][0], h0s[p0][1],
            Wsm[1][0], Wsm[1][1], Wb[3][0], Wb[3][1],
            dbih0, dbhh0, h0f[p0], h0f[1 - p0],
            h0s[1 - p0][0], h0s[1 - p0][1],
            hidden + (size_t)t * 2 * H, hid_ld);
        p0 ^= 1;
        gru_step_mma<<<grid, NTHR, SMEM_BYTES>>>(
            h0s[p0][0], h0s[p0][1], NC_H,
            h1s[p1][0], h1s[p1][1],
            Wb[4][0], Wb[4][1], Wb[5][0], Wb[5][1],
            dbih1, dbhh1, h1f[p1], h1f[1 - p1],
            h1s[1 - p1][0], h1s[1 - p1][1],
            hidden + (size_t)t * 2 * H + H, hid_ld);
        p1 ^= 1;
        linear_kernel<<<BATCH / 8, 256>>>(h1f[p1], linW, linb,
                                          outputs + (size_t)t * OUT_DIM, out_ld,
                                          xd[0], xd[1]);
    }
}

// round 5
// speedup vs baseline: 3.0488x; 1.6910x over previous
#include <cuda_runtime.h>
#include <cuda_bf16.h>
#include <math.h>
#include <stdint.h>

// ---------------- problem constants ----------------
#define BATCH 512
#define T_IN 64
#define IN_DIM 16
#define HS 32
#define OUT_DIM 32
#define H 960
#define G3 2880
#define T_PRED 48

#define NC_H 15             // 960/64 K-chunks
#define MTILE 128
#define NTILE 96            // 3 gates x 32 units
#define NTHR 256

// smem: [bias 1024B][3 stages]; fp32 rows: 64 elems + 4 pad = 272B
#define ROWB 272
#define ABYTES (MTILE * ROWB)      // 34816
#define BBYTES (NTILE * ROWB)      // 26112
#define STAGE (ABYTES + BBYTES)    // 60928
#define SMEM_BYTES (1024 + 3 * STAGE)   // 183808
// epilogue planes (reuse stage area)
#define MSTRIDE 100
#define N2STRIDE 36
#define N2OFF 51200

// ---------------- device scratch ----------------
#define WBIG (G3 * NC_H * 64)
#define WSM  (G3 * 64)
#define HSN  (NC_H * BATCH * 64)

__device__ float g_W[6][WBIG];      // tf32-rounded: eWhh0,eWih1,eWhh1,dWhh0,dWih1,dWhh1
__device__ float g_Wsm[2][WSM];     // eWih0, dWih0
__device__ float g_h0f[2][BATCH * H];
__device__ float g_h1f[2][BATCH * H];
__device__ float g_h0a[2][HSN];     // tf32-rounded A-planes (ping-pong)
__device__ float g_h1a[2][HSN];
__device__ float g_xin[T_IN * BATCH * 64];
__device__ float g_ll[BATCH * 64];
__device__ float g_xd[BATCH * 64];

// ---------------- helpers ----------------
__device__ __forceinline__ uint32_t smem_u32(const void* p) {
    uint32_t a;
    asm("{ .reg .u64 t; cvta.to.shared.u64 t, %1; cvt.u32.u64 %0, t; }" : "=r"(a) : "l"(p));
    return a;
}
__device__ __forceinline__ void cp16(uint32_t dst, const void* src) {
    asm volatile("cp.async.cg.shared.global [%0], [%1], 16;" :: "r"(dst), "l"(src) : "memory");
}
#define CP_COMMIT() asm volatile("cp.async.commit_group;" ::: "memory")
#define CP_WAIT(n)  asm volatile("cp.async.wait_group %0;" :: "n"(n) : "memory")

__device__ __forceinline__ uint32_t lds32(uint32_t a) {
    uint32_t v;
    asm volatile("ld.shared.b32 %0, [%1];" : "=r"(v) : "r"(a));
    return v;
}
__device__ __forceinline__ void mma_tf32(float (&d)[4], const uint32_t (&a)[4],
                                         uint32_t b0, uint32_t b1) {
    asm volatile(
        "mma.sync.aligned.m16n8k8.row.col.f32.tf32.tf32.f32 "
        "{%0,%1,%2,%3}, {%4,%5,%6,%7}, {%8,%9}, {%0,%1,%2,%3};"
        : "+f"(d[0]), "+f"(d[1]), "+f"(d[2]), "+f"(d[3])
        : "r"(a[0]), "r"(a[1]), "r"(a[2]), "r"(a[3]), "r"(b0), "r"(b1));
}
__device__ __forceinline__ float tf32r(float v) {
    uint32_t o;
    asm("cvt.rna.tf32.f32 %0, %1;" : "=r"(o) : "f"(v));
    return __uint_as_float(o);
}
__device__ __forceinline__ float sigf(float v) { return 1.0f / (1.0f + expf(-v)); }

// ---------------- fused GRU step (mma.sync tf32, single pass) ----------------
__global__ __launch_bounds__(NTHR, 1)
void gru_step_tf(const float* __restrict__ xA, int ncx,
                 const float* __restrict__ hA,
                 const float* __restrict__ w1, const float* __restrict__ w2,
                 const float* __restrict__ bih, const float* __restrict__ bhh,
                 const float* __restrict__ hprevf, float* __restrict__ houtf,
                 float* __restrict__ hAout,
                 float* __restrict__ hcat, int hcat_ld)
{
    extern __shared__ char smem[];
    float* sbias = (float*)smem;
    const uint32_t sb = smem_u32(smem);

    const int tid  = threadIdx.x;
    const int lane = tid & 31;
    const int w    = tid >> 5;
    const int wm   = w & 3;      // m-block (32 rows)
    const int wn   = w >> 2;     // n-half (48 cols)
    const int m0   = blockIdx.x * MTILE;
    const int ub   = blockIdx.y;
    const int nc   = ncx + NC_H;

    if (tid < 192) {
        int g = (tid < 96) ? (tid >> 5) : ((tid - 96) >> 5);
        int j = tid & 31;
        sbias[tid] = (tid < 96) ? bih[g * H + ub * 32 + j] : bhh[g * H + ub * 32 + j];
    }

    // acc = r/z (both passes) + n-gate x-pass; accn = n-gate h-pass (wn==1 only)
    float acc[2][6][4];
    float accn[2][4][4];
#pragma unroll
    for (int m2 = 0; m2 < 2; ++m2) {
#pragma unroll
        for (int f = 0; f < 6; ++f)
#pragma unroll
            for (int i = 0; i < 4; ++i) acc[m2][f][i] = 0.f;
#pragma unroll
        for (int f = 0; f < 4; ++f)
#pragma unroll
            for (int i = 0; i < 4; ++i) accn[m2][f][i] = 0.f;
    }

    // fragment lane offsets (bytes, within stage)
    const uint32_t aoff = (uint32_t)(wm * 32 + (lane >> 2)) * ROWB + (lane & 3) * 4;
    const uint32_t boff = ABYTES + (uint32_t)(wn * 48 + (lane >> 2)) * ROWB + (lane & 3) * 4;

    auto issue_load = [&](int c) {
        const float* ap = (c < ncx) ? (xA + ((size_t)c * BATCH + m0) * 64)
                                    : (hA + ((size_t)(c - ncx) * BATCH + m0) * 64);
        const float* bp = (c < ncx) ? (w1 + ((size_t)c * G3 + ub * NTILE) * 64)
                                    : (w2 + ((size_t)(c - ncx) * G3 + ub * NTILE) * 64);
        const char* asrc = (const char*)ap;
        const char* bsrc = (const char*)bp;
        uint32_t d = sb + 1024 + (uint32_t)(c % 3) * STAGE;
#pragma unroll
        for (int i = 0; i < 8; ++i) {              // A: 2048 x 16B
            int u = tid + i * NTHR;
            cp16(d + (u >> 4) * ROWB + (u & 15) * 16, asrc + (size_t)u * 16);
        }
#pragma unroll
        for (int i = 0; i < 6; ++i) {              // B: 1536 x 16B
            int u = tid + i * NTHR;
            cp16(d + ABYTES + (u >> 4) * ROWB + (u & 15) * 16, bsrc + (size_t)u * 16);
        }
        CP_COMMIT();
    };

    issue_load(0); issue_load(1); issue_load(2);

#define CHUNK_BODY(SPLIT)                                                       \
    {                                                                           \
        _Pragma("unroll")                                                       \
        for (int kk = 0; kk < 8; ++kk) {                                        \
            uint32_t a[2][4];                                                   \
            _Pragma("unroll")                                                   \
            for (int mb = 0; mb < 2; ++mb) {                                    \
                uint32_t ab = stage + aoff + mb * (16 * ROWB) + kk * 32;        \
                a[mb][0] = lds32(ab);                                           \
                a[mb][1] = lds32(ab + 8 * ROWB);                                \
                a[mb][2] = lds32(ab + 16);                                      \
                a[mb][3] = lds32(ab + 8 * ROWB + 16);                           \
            }                                                                   \
            _Pragma("unroll")                                                   \
            for (int nb = 0; nb < 6; ++nb) {                                    \
                uint32_t bb = stage + boff + nb * (8 * ROWB) + kk * 32;         \
                uint32_t b0 = lds32(bb), b1 = lds32(bb + 16);                   \
                if (SPLIT && nb >= 2) {                                         \
                    mma_tf32(accn[0][nb - 2], a[0], b0, b1);                    \
                    mma_tf32(accn[1][nb - 2], a[1], b0, b1);                    \
                } else {                                                        \
                    mma_tf32(acc[0][nb], a[0], b0, b1);                         \
                    mma_tf32(acc[1][nb], a[1], b0, b1);                         \
                }                                                               \
            }                                                                   \
        }                                                                       \
    }

    for (int c = 0; c < nc; ++c) {
        if (c + 2 < nc)      { CP_WAIT(2); }
        else if (c + 1 < nc) { CP_WAIT(1); }
        else                 { CP_WAIT(0); }
        __syncthreads();
        const uint32_t stage = sb + 1024 + (uint32_t)(c % 3) * STAGE;
        if (c >= ncx && wn == 1) CHUNK_BODY(1) else CHUNK_BODY(0)
        __syncthreads();
        if (c + 3 < nc) issue_load(c + 3);
    }
#undef CHUNK_BODY

    // ---------------- epilogue: accums -> smem planes -> gate math ----------------
    float* Mp = (float*)(smem + 1024);
    float* Np = (float*)(smem + 1024 + N2OFF);
    {
        const int rb = wm * 32 + (lane >> 2);
        const int cb = wn * 48 + (lane & 3) * 2;
#pragma unroll
        for (int m2 = 0; m2 < 2; ++m2) {
#pragma unroll
            for (int f = 0; f < 6; ++f) {
                int r = rb + m2 * 16;
                int cc = cb + f * 8;
                *(float2*)&Mp[r * MSTRIDE + cc]       = make_float2(acc[m2][f][0], acc[m2][f][1]);
                *(float2*)&Mp[(r + 8) * MSTRIDE + cc] = make_float2(acc[m2][f][2], acc[m2][f][3]);
            }
        }
        if (wn == 1) {
            const int cb2 = (lane & 3) * 2;
#pragma unroll
            for (int m2 = 0; m2 < 2; ++m2) {
#pragma unroll
                for (int f = 0; f < 4; ++f) {
                    int r = rb + m2 * 16;
                    int cc = cb2 + f * 8;
                    *(float2*)&Np[r * N2STRIDE + cc]       = make_float2(accn[m2][f][0], accn[m2][f][1]);
                    *(float2*)&Np[(r + 8) * N2STRIDE + cc] = make_float2(accn[m2][f][2], accn[m2][f][3]);
                }
            }
        }
    }
    __syncthreads();

    {
        const int row = tid >> 1;
        const int j0  = (tid & 1) * 16;
        const int brow = m0 + row;
        const int cj = ub >> 1;
        const int kb = (ub & 1) * 32;

        float hv[16];
#pragma unroll
        for (int v = 0; v < 8; ++v) {
            int j = j0 + v * 2;
            float2 R  = *(float2*)&Mp[row * MSTRIDE + j];
            float2 Z  = *(float2*)&Mp[row * MSTRIDE + 32 + j];
            float2 NX = *(float2*)&Mp[row * MSTRIDE + 64 + j];
            float2 NH = *(float2*)&Np[row * N2STRIDE + j];
            float2 HP = *(const float2*)(hprevf + (size_t)brow * H + ub * 32 + j);
#pragma unroll
            for (int e = 0; e < 2; ++e) {
                int jj = j + e;
                float rr = sigf(((e ? R.y : R.x))  + sbias[jj]      + sbias[96 + jj]);
                float zz = sigf(((e ? Z.y : Z.x))  + sbias[32 + jj] + sbias[128 + jj]);
                float nn = tanhf(((e ? NX.y : NX.x)) + sbias[64 + jj]
                                 + rr * (((e ? NH.y : NH.x)) + sbias[160 + jj]));
                hv[j - j0 + e] = (1.0f - zz) * nn + zz * (e ? HP.y : HP.x);
            }
        }
        const size_t ob = (size_t)brow * H + ub * 32 + j0;
#pragma unroll
        for (int q = 0; q < 4; ++q)
            *(float4*)(houtf + ob + q * 4) = make_float4(hv[q*4], hv[q*4+1], hv[q*4+2], hv[q*4+3]);
        if (hcat) {
            const size_t cbo = (size_t)brow * hcat_ld + ub * 32 + j0;
#pragma unroll
            for (int q = 0; q < 4; ++q)
                *(float4*)(hcat + cbo + q * 4) = make_float4(hv[q*4], hv[q*4+1], hv[q*4+2], hv[q*4+3]);
        }
        // tf32-rounded A-plane for next step
        const size_t so = ((size_t)cj * BATCH + brow) * 64 + kb + j0;
#pragma unroll
        for (int q = 0; q < 4; ++q)
            *(float4*)(hAout + so + q * 4) = make_float4(tf32r(hv[q*4]), tf32r(hv[q*4+1]),
                                                         tf32r(hv[q*4+2]), tf32r(hv[q*4+3]));
    }
}

// ---------------- linear head ----------------
__global__ __launch_bounds__(256)
void linear_kernel(const float* __restrict__ h,
                   const float* __restrict__ W, const float* __restrict__ bias,
                   float* __restrict__ out, int out_ld,
                   float* __restrict__ xdA)
{
    __shared__ float Ws[64][33];
    __shared__ float hs[8][64];
    const int tid = threadIdx.x;
    const int o = tid & 31;
    const int bl = tid >> 5;
    const int b0 = blockIdx.x * 8;

    float acc = 0.f;
    for (int k0 = 0; k0 < H; k0 += 64) {
#pragma unroll
        for (int i = 0; i < 8; ++i) {
            int idx = tid + i * 256;
            Ws[idx & 63][idx >> 6] = W[(size_t)(idx >> 6) * H + k0 + (idx & 63)];
        }
#pragma unroll
        for (int i = 0; i < 2; ++i) {
            int idx = tid + i * 256;
            hs[idx >> 6][idx & 63] = h[(size_t)(b0 + (idx >> 6)) * H + k0 + (idx & 63)];
        }
        __syncthreads();
#pragma unroll
        for (int kk = 0; kk < 64; ++kk)
            acc = fmaf(hs[bl][kk], Ws[kk][o], acc);
        __syncthreads();
    }
    float v = acc + bias[o];
    int b = b0 + bl;
    out[(size_t)b * out_ld + o] = v;
    xdA[(size_t)b * 64 + o] = tf32r(v);
}

// ---------------- prep kernels ----------------
__global__ void prep_weight(const float* __restrict__ W, int K, int nch,
                            float* __restrict__ Wt)
{
    int total = G3 * nch * 64;
    for (int idx = blockIdx.x * blockDim.x + threadIdx.x; idx < total; idx += gridDim.x * blockDim.x) {
        int k = idx & 63;
        int q = idx >> 6;
        int n = q % G3;
        int c = q / G3;
        int ubl = n / 96, rem = n % 96, g = rem >> 5, jj = rem & 31;
        int row = g * H + ubl * 32 + jj;
        int col = c * 64 + k;
        float v = (col < K) ? W[(size_t)row * K + col] : 0.f;
        Wt[idx] = tf32r(v);
    }
}

__global__ void prep_in(const float* __restrict__ in_data, float* __restrict__ A)
{
    int total = T_IN * BATCH * 64;
    for (int idx = blockIdx.x * blockDim.x + threadIdx.x; idx < total; idx += gridDim.x * blockDim.x) {
        int k = idx & 63;
        int q = idx >> 6;
        int b = q & (BATCH - 1);
        int t = q >> 9;
        float v = (k < IN_DIM) ? in_data[((size_t)b * T_IN + t) * IN_DIM + k] : 0.f;
        A[idx] = tf32r(v);
    }
}

__global__ void prep_ll(const float* __restrict__ ll_src, float* __restrict__ A)
{
    int total = BATCH * 64;
    for (int idx = blockIdx.x * blockDim.x + threadIdx.x; idx < total; idx += gridDim.x * blockDim.x) {
        int k = idx & 63;
        int b = idx >> 6;
        float v = (k < HS) ? ll_src[(size_t)b * HS + k] : 0.f;
        A[idx] = tf32r(v);
    }
}

// ---------------- host ----------------
extern "C" void kernel_launch(void* const* d_in, const int* in_sizes, int n_in,
                              void* d_out, int out_size)
{
    const float* in_data  = (const float*)d_in[0];
    const float* last_loc = (const float*)d_in[1];
    const float* eWih0 = (const float*)d_in[3];
    const float* eWhh0 = (const float*)d_in[4];
    const float* ebih0 = (const float*)d_in[5];
    const float* ebhh0 = (const float*)d_in[6];
    const float* eWih1 = (const float*)d_in[7];
    const float* eWhh1 = (const float*)d_in[8];
    const float* ebih1 = (const float*)d_in[9];
    const float* ebhh1 = (const float*)d_in[10];
    const float* dWih0 = (const float*)d_in[11];
    const float* dWhh0 = (const float*)d_in[12];
    const float* dbih0 = (const float*)d_in[13];
    const float* dbhh0 = (const float*)d_in[14];
    const float* dWih1 = (const float*)d_in[15];
    const float* dWhh1 = (const float*)d_in[16];
    const float* dbih1 = (const float*)d_in[17];
    const float* dbhh1 = (const float*)d_in[18];
    const float* linW  = (const float*)d_in[19];
    const float* linb  = (const float*)d_in[20];

    float* outputs = (float*)d_out;
    float* hidden  = (float*)d_out + (size_t)BATCH * T_PRED * OUT_DIM;

    float (*Wb)[WBIG];          cudaGetSymbolAddress((void**)&Wb, g_W);
    float (*Wsm)[WSM];          cudaGetSymbolAddress((void**)&Wsm, g_Wsm);
    float (*h0f)[BATCH * H];    cudaGetSymbolAddress((void**)&h0f, g_h0f);
    float (*h1f)[BATCH * H];    cudaGetSymbolAddress((void**)&h1f, g_h1f);
    float (*h0a)[HSN];          cudaGetSymbolAddress((void**)&h0a, g_h0a);
    float (*h1a)[HSN];          cudaGetSymbolAddress((void**)&h1a, g_h1a);
    float* xin = nullptr;       cudaGetSymbolAddress((void**)&xin, g_xin);
    float* xll = nullptr;       cudaGetSymbolAddress((void**)&xll, g_ll);
    float* xd  = nullptr;       cudaGetSymbolAddress((void**)&xd, g_xd);

    cudaFuncSetAttribute(gru_step_tf, cudaFuncAttributeMaxDynamicSharedMemorySize, SMEM_BYTES);

    prep_weight<<<1024, 256>>>(eWhh0, H,  NC_H, Wb[0]);
    prep_weight<<<1024, 256>>>(eWih1, H,  NC_H, Wb[1]);
    prep_weight<<<1024, 256>>>(eWhh1, H,  NC_H, Wb[2]);
    prep_weight<<<1024, 256>>>(dWhh0, H,  NC_H, Wb[3]);
    prep_weight<<<1024, 256>>>(dWih1, H,  NC_H, Wb[4]);
    prep_weight<<<1024, 256>>>(dWhh1, H,  NC_H, Wb[5]);
    prep_weight<<<256, 256>>>(eWih0, IN_DIM, 1, Wsm[0]);
    prep_weight<<<256, 256>>>(dWih0, HS,     1, Wsm[1]);
    prep_in<<<512, 256>>>(in_data, xin);
    prep_ll<<<64, 256>>>(last_loc, xll);

    cudaMemsetAsync(h0f[0], 0, (size_t)BATCH * H * sizeof(float));
    cudaMemsetAsync(h1f[0], 0, (size_t)BATCH * H * sizeof(float));
    cudaMemsetAsync(h0a[0], 0, (size_t)HSN * sizeof(float));
    cudaMemsetAsync(h1a[0], 0, (size_t)HSN * sizeof(float));
    cudaMemsetAsync(xd,     0, (size_t)BATCH * 64 * sizeof(float));

    dim3 grid(BATCH / MTILE, H / 32);   // (4, 30)
    int p0 = 0, p1 = 0;
    const int out_ld = T_PRED * OUT_DIM;
    const int hid_ld = T_PRED * 2 * H;

    // ---- encoder ----
    for (int t = 0; t < T_IN; ++t) {
        gru_step_tf<<<grid, NTHR, SMEM_BYTES>>>(
            xin + (size_t)t * BATCH * 64, 1,
            h0a[p0], Wsm[0], Wb[0],
            ebih0, ebhh0, h0f[p0], h0f[1 - p0], h0a[1 - p0],
            nullptr, 0);
        p0 ^= 1;
        gru_step_tf<<<grid, NTHR, SMEM_BYTES>>>(
            h0a[p0], NC_H,
            h1a[p1], Wb[1], Wb[2],
            ebih1, ebhh1, h1f[p1], h1f[1 - p1], h1a[1 - p1],
            nullptr, 0);
        p1 ^= 1;
    }

    // ---- decoder ----
    for (int t = 0; t < T_PRED; ++t) {
        const float* xAp = (t == 0) ? xll : xd;
        gru_step_tf<<<grid, NTHR, SMEM_BYTES>>>(
            xAp, 1,
            h0a[p0], Wsm[1], Wb[3],
            dbih0, dbhh0, h0f[p0], h0f[1 - p0], h0a[1 - p0],
            hidden + (size_t)t * 2 * H, hid_ld);
        p0 ^= 1;
        gru_step_tf<<<grid, NTHR, SMEM_BYTES>>>(
            h0a[p0], NC_H,
            h1a[p1], Wb[4], Wb[5],
            dbih1, dbhh1, h1f[p1], h1f[1 - p1], h1a[1 - p1],
            hidden + (size_t)t * 2 * H + H, hid_ld);
        p1 ^= 1;
        linear_kernel<<<BATCH / 8, 256>>>(h1f[p1], linW, linb,
                                          outputs + (size_t)t * OUT_DIM, out_ld, xd);
    }
}